// round 2
// baseline (speedup 1.0000x reference)
#include <cuda_runtime.h>
#include <math.h>

// Problem constants
#define BATCH 16384
#define HID   512
#define SEQ   6
// attn_in width = 2H + O = 1025 ; comb in width = H + O = 513 ; gates N = 4H = 2048

// ---------------- scratch (device globals; no allocations allowed) ----------
__device__ float g_attn_applied[(size_t)BATCH * HID];          // 33.5 MB
__device__ float g_x[(size_t)BATCH * HID];                     // 33.5 MB
__device__ float g_gates[(size_t)BATCH * 4 * HID];             // 128 MB
__device__ float g_Wc2[HID * HID];                             // repacked W_comb[:,1:]
__device__ float g_wc0[HID];                                   // W_comb[:,0]

// ---------------- K0: repack W_comb ----------------------------------------
__global__ void pack_wcomb_kernel(const float* __restrict__ W_comb) {
    int i = blockIdx.x * 256 + threadIdx.x;
    if (i < HID * HID) {
        int n = i / HID, k = i % HID;
        g_Wc2[i] = W_comb[n * 513 + 1 + k];
    }
    if (i < HID) g_wc0[i] = W_comb[i * 513];
}

// ---------------- K1: attention logits + softmax + weighted sum -------------
__global__ void attn_kernel(const float* __restrict__ input,
                            const float* __restrict__ hidden,
                            const float* __restrict__ cell,
                            const float* __restrict__ enc,
                            const float* __restrict__ W_attn,
                            const float* __restrict__ b_attn,
                            float* __restrict__ out_attnw) {
    int b = blockIdx.x;
    int t = threadIdx.x;  // 128 threads
    __shared__ float red[SEQ][128];
    __shared__ float ws[SEQ];

    const float* hrow = hidden + (size_t)b * HID;
    const float* crow = cell + (size_t)b * HID;

    float p[SEQ];
#pragma unroll
    for (int s = 0; s < SEQ; s++) p[s] = 0.f;

    for (int k = t; k < HID; k += 128) {
        float hv = hrow[k], cv = crow[k];
#pragma unroll
        for (int s = 0; s < SEQ; s++) {
            p[s] += hv * W_attn[s * 1025 + 1 + k] + cv * W_attn[s * 1025 + 513 + k];
        }
    }
#pragma unroll
    for (int s = 0; s < SEQ; s++) red[s][t] = p[s];
    __syncthreads();
    for (int off = 64; off > 0; off >>= 1) {
        if (t < off) {
#pragma unroll
            for (int s = 0; s < SEQ; s++) red[s][t] += red[s][t + off];
        }
        __syncthreads();
    }
    if (t == 0) {
        float inp = input[b];
        float lo[SEQ];
        float mx = -1e30f;
#pragma unroll
        for (int s = 0; s < SEQ; s++) {
            lo[s] = red[s][0] + b_attn[s] + inp * W_attn[s * 1025];
            mx = fmaxf(mx, lo[s]);
        }
        float sum = 0.f;
#pragma unroll
        for (int s = 0; s < SEQ; s++) { lo[s] = expf(lo[s] - mx); sum += lo[s]; }
        float inv = 1.f / sum;
#pragma unroll
        for (int s = 0; s < SEQ; s++) {
            float w = lo[s] * inv;
            ws[s] = w;
            out_attnw[(size_t)b * SEQ + s] = w;
        }
    }
    __syncthreads();

    const float* eb = enc + (size_t)b * SEQ * HID;
    float w0 = ws[0], w1 = ws[1], w2 = ws[2], w3 = ws[3], w4 = ws[4], w5 = ws[5];
    for (int h = t; h < HID; h += 128) {
        float acc = w0 * eb[0 * HID + h] + w1 * eb[1 * HID + h] + w2 * eb[2 * HID + h]
                  + w3 * eb[3 * HID + h] + w4 * eb[4 * HID + h] + w5 * eb[5 * HID + h];
        g_attn_applied[(size_t)b * HID + h] = acc;
    }
}

// ---------------- generic tiled fp32 GEMM (NT: both operands K-major) -------
// C[m,n] = epilogue( sum_k A[m,k] * W[n,k] )
// Runs as (at most) two K-segments of 512 each: (A1,W1) then (A2,W2).
// BM=BN=128, BK=16, 256 threads, 8x8 per thread.
// MODE 0: C = relu(acc + bias1[n] + rvec_m[m]*rvec_n[n])   (attn_combine)
// MODE 1: C = acc + bias1[n] + bias2[n]                     (gates)
template <int MODE>
__device__ __forceinline__ void gemm_segment(
    const float* __restrict__ Ap, const float* __restrict__ Wp,
    int RM, int CN, int tid, float* As, float* Ws, float acc[8][8]) {
    const int tx = tid & 15;
    const int ty = tid >> 4;
#pragma unroll 1
    for (int kk = 0; kk < 512; kk += 16) {
        // load A tile: 128 rows x 16 k, as float4 (512 float4s, 2 iters)
#pragma unroll
        for (int it = 0; it < 2; it++) {
            int e = it * 256 + tid;
            int row = e >> 2;
            int kq = e & 3;
            float4 v = *(const float4*)(Ap + (size_t)(RM + row) * 512 + kk + kq * 4);
            int kb = kq * 4;
            As[(kb + 0) * 132 + row] = v.x;
            As[(kb + 1) * 132 + row] = v.y;
            As[(kb + 2) * 132 + row] = v.z;
            As[(kb + 3) * 132 + row] = v.w;
        }
        // load W tile: 128 cols x 16 k
#pragma unroll
        for (int it = 0; it < 2; it++) {
            int e = it * 256 + tid;
            int row = e >> 2;
            int kq = e & 3;
            float4 v = *(const float4*)(Wp + (size_t)(CN + row) * 512 + kk + kq * 4);
            int kb = kq * 4;
            Ws[(kb + 0) * 132 + row] = v.x;
            Ws[(kb + 1) * 132 + row] = v.y;
            Ws[(kb + 2) * 132 + row] = v.z;
            Ws[(kb + 3) * 132 + row] = v.w;
        }
        __syncthreads();

        const float4* As4 = (const float4*)As;
        const float4* Ws4 = (const float4*)Ws;
#pragma unroll
        for (int k = 0; k < 16; k++) {
            float4 a0 = As4[k * 33 + ty * 2];
            float4 a1 = As4[k * 33 + ty * 2 + 1];
            float4 w0 = Ws4[k * 33 + tx * 2];
            float4 w1 = Ws4[k * 33 + tx * 2 + 1];
            float a[8] = {a0.x, a0.y, a0.z, a0.w, a1.x, a1.y, a1.z, a1.w};
            float w[8] = {w0.x, w0.y, w0.z, w0.w, w1.x, w1.y, w1.z, w1.w};
#pragma unroll
            for (int i = 0; i < 8; i++)
#pragma unroll
                for (int j = 0; j < 8; j++) acc[i][j] += a[i] * w[j];
        }
        __syncthreads();
    }
}

template <int MODE, int NSEG>
__global__ void __launch_bounds__(256, 2)
gemm_kernel(const float* __restrict__ A1, const float* __restrict__ A2,
            const float* __restrict__ W1, const float* __restrict__ W2,
            const float* __restrict__ bias1, const float* __restrict__ bias2,
            const float* __restrict__ rvec_m, const float* __restrict__ rvec_n,
            float* __restrict__ C, int ldc) {
    const int tid = threadIdx.x;
    const int tx = tid & 15;   // col group
    const int ty = tid >> 4;   // row group
    const int RM = blockIdx.x * 128;
    const int CN = blockIdx.y * 128;

    __shared__ __align__(16) float As[16 * 132];
    __shared__ __align__(16) float Ws[16 * 132];

    float acc[8][8];
#pragma unroll
    for (int i = 0; i < 8; i++)
#pragma unroll
        for (int j = 0; j < 8; j++) acc[i][j] = 0.f;

    gemm_segment<MODE>(A1, W1, RM, CN, tid, As, Ws, acc);
    if (NSEG == 2) gemm_segment<MODE>(A2, W2, RM, CN, tid, As, Ws, acc);

    // epilogue
    float bn[8], b2[8], rn[8];
#pragma unroll
    for (int j = 0; j < 8; j++) {
        int n = CN + tx * 8 + j;
        bn[j] = bias1[n];
        if (MODE == 1) b2[j] = bias2[n];
        if (MODE == 0) rn[j] = rvec_n[n];
    }
#pragma unroll
    for (int i = 0; i < 8; i++) {
        int m = RM + ty * 8 + i;
        float rm = (MODE == 0) ? rvec_m[m] : 0.f;
        float out[8];
#pragma unroll
        for (int j = 0; j < 8; j++) {
            float v = acc[i][j] + bn[j];
            if (MODE == 0) {
                v += rm * rn[j];
                v = fmaxf(v, 0.f);
            } else {
                v += b2[j];
            }
            out[j] = v;
        }
        float4* dst = (float4*)(C + (size_t)m * ldc + CN + tx * 8);
        dst[0] = make_float4(out[0], out[1], out[2], out[3]);
        dst[1] = make_float4(out[4], out[5], out[6], out[7]);
    }
}

// ---------------- K4: LSTM elementwise + output GEMV ------------------------
__global__ void lstm_kernel(const float* __restrict__ cell,
                            const float* __restrict__ W_out,
                            const float* __restrict__ b_out,
                            float* __restrict__ out_y,
                            float* __restrict__ out_h,
                            float* __restrict__ out_c) {
    int b = blockIdx.x;
    int t = threadIdx.x;  // 128
    const float* g = g_gates + (size_t)b * 2048;
    const float* crow = cell + (size_t)b * HID;
    float partial = 0.f;
    for (int h = t; h < HID; h += 128) {
        float iv = g[h];
        float fv = g[512 + h];
        float gv = g[1024 + h];
        float ov = g[1536 + h];
        float si = 1.f / (1.f + expf(-iv));
        float sf = 1.f / (1.f + expf(-fv));
        float so = 1.f / (1.f + expf(-ov));
        float cn = sf * crow[h] + si * tanhf(gv);
        float hn = so * tanhf(cn);
        out_c[(size_t)b * HID + h] = cn;
        out_h[(size_t)b * HID + h] = hn;
        partial += hn * W_out[h];
    }
    __shared__ float red[128];
    red[t] = partial;
    __syncthreads();
    for (int off = 64; off > 0; off >>= 1) {
        if (t < off) red[t] += red[t + off];
        __syncthreads();
    }
    if (t == 0) out_y[b] = red[0] + b_out[0];
}

// ---------------- launch -----------------------------------------------------
extern "C" void kernel_launch(void* const* d_in, const int* in_sizes, int n_in,
                              void* d_out, int out_size) {
    const float* input   = (const float*)d_in[0];   // [B,1]
    const float* hidden  = (const float*)d_in[1];   // [B,H]
    const float* cell    = (const float*)d_in[2];   // [B,H]
    const float* enc     = (const float*)d_in[3];   // [B,S,H]
    const float* W_attn  = (const float*)d_in[4];   // [S,1025]
    const float* b_attn  = (const float*)d_in[5];   // [S]
    const float* W_comb  = (const float*)d_in[6];   // [H,513]
    const float* b_comb  = (const float*)d_in[7];   // [H]
    const float* W_ih    = (const float*)d_in[8];   // [4H,H]
    const float* W_hh    = (const float*)d_in[9];   // [4H,H]
    const float* b_ih    = (const float*)d_in[10];  // [4H]
    const float* b_hh    = (const float*)d_in[11];  // [4H]
    const float* W_out   = (const float*)d_in[12];  // [1,H]
    const float* b_out   = (const float*)d_in[13];  // [1]

    float* out = (float*)d_out;
    float* out_y  = out;                                   // [B]
    float* out_h  = out + BATCH;                           // [B,H]
    float* out_c  = out + BATCH + (size_t)BATCH * HID;     // [B,H]
    float* out_aw = out + BATCH + 2 * (size_t)BATCH * HID; // [B,S]

    // scratch symbol pointers (device globals; query is host-side, capture-safe)
    float* p_attn_applied; cudaGetSymbolAddress((void**)&p_attn_applied, g_attn_applied);
    float* p_x;            cudaGetSymbolAddress((void**)&p_x, g_x);
    float* p_gates;        cudaGetSymbolAddress((void**)&p_gates, g_gates);
    float* p_Wc2;          cudaGetSymbolAddress((void**)&p_Wc2, g_Wc2);
    float* p_wc0;          cudaGetSymbolAddress((void**)&p_wc0, g_wc0);

    // K0: repack W_comb
    pack_wcomb_kernel<<<(HID * HID + 255) / 256, 256>>>(W_comb);

    // K1: attention
    attn_kernel<<<BATCH, 128>>>(input, hidden, cell, enc, W_attn, b_attn, out_aw);

    // K2: attn_combine  (M=16384, N=512, K=512) -> g_x
    {
        dim3 grid(BATCH / 128, HID / 128);
        gemm_kernel<0, 1><<<grid, 256>>>(p_attn_applied, nullptr,
                                         p_Wc2, nullptr,
                                         b_comb, nullptr,
                                         input, p_wc0,
                                         p_x, HID);
    }

    // K3: gates (M=16384, N=2048, K=1024: [x|hidden] @ [W_ih|W_hh]^T) -> g_gates
    {
        dim3 grid(BATCH / 128, (4 * HID) / 128);
        gemm_kernel<1, 2><<<grid, 256>>>(p_x, hidden,
                                         W_ih, W_hh,
                                         b_ih, b_hh,
                                         nullptr, nullptr,
                                         p_gates, 4 * HID);
    }

    // K4: LSTM elementwise + output
    lstm_kernel<<<BATCH, 128>>>(cell, W_out, b_out, out_y, out_h, out_c);
}

// round 17
// speedup vs baseline: 1.6398x; 1.6398x over previous
#include <cuda_runtime.h>
#include <math.h>
#include <stdint.h>

#define BATCH 16384
#define HID   512
#define SEQ   6

// ---------------- scratch (device globals) ----------------------------------
__device__ float g_attn_applied[(size_t)BATCH * HID];
__device__ float g_x[(size_t)BATCH * HID];
__device__ float g_gates[(size_t)BATCH * 4 * HID];
__device__ float g_Wc2[HID * HID];
__device__ float g_wc0[HID];

// split a float4 into bf16 hi pairs + bf16 lo (residual) pairs, element order preserved
__device__ __forceinline__ void split4(float4 v, uint32_t& h01, uint32_t& h23,
                                       uint32_t& l01, uint32_t& l23) {
    asm("cvt.rn.bf16x2.f32 %0, %1, %2;" : "=r"(h01) : "f"(v.y), "f"(v.x));
    asm("cvt.rn.bf16x2.f32 %0, %1, %2;" : "=r"(h23) : "f"(v.w), "f"(v.z));
    float h0 = __uint_as_float(h01 << 16);
    float h1 = __uint_as_float(h01 & 0xffff0000u);
    float h2 = __uint_as_float(h23 << 16);
    float h3 = __uint_as_float(h23 & 0xffff0000u);
    float l0 = v.x - h0, l1 = v.y - h1, l2 = v.z - h2, l3 = v.w - h3;
    asm("cvt.rn.bf16x2.f32 %0, %1, %2;" : "=r"(l01) : "f"(l1), "f"(l0));
    asm("cvt.rn.bf16x2.f32 %0, %1, %2;" : "=r"(l23) : "f"(l3), "f"(l2));
}

// mma.sync m16n8k16 bf16 (sm_80+; no 'a'-gated features)
#define MMA16816(d, a, b0, b1) \
    asm volatile("mma.sync.aligned.m16n8k16.row.col.f32.bf16.bf16.f32 " \
        "{%0,%1,%2,%3}, {%4,%5,%6,%7}, {%8,%9}, {%0,%1,%2,%3};" \
        : "+f"((d)[0]), "+f"((d)[1]), "+f"((d)[2]), "+f"((d)[3]) \
        : "r"((a)[0]), "r"((a)[1]), "r"((a)[2]), "r"((a)[3]), "r"(b0), "r"(b1))

// ---------------- K0: repack W_comb ------------------------------------------
__global__ void pack_wcomb_kernel(const float* __restrict__ W_comb) {
    int i = blockIdx.x * 256 + threadIdx.x;
    if (i < HID * HID) {
        int n = i / HID, k = i % HID;
        g_Wc2[i] = W_comb[n * 513 + 1 + k];
    }
    if (i < HID) g_wc0[i] = W_comb[i * 513];
}

// ---------------- K1: attention ----------------------------------------------
__global__ void attn_kernel(const float* __restrict__ input,
                            const float* __restrict__ hidden,
                            const float* __restrict__ cell,
                            const float* __restrict__ enc,
                            const float* __restrict__ W_attn,
                            const float* __restrict__ b_attn,
                            float* __restrict__ out_attnw) {
    int b = blockIdx.x;
    int t = threadIdx.x;  // 128
    __shared__ float red[SEQ][128];
    __shared__ float ws[SEQ];

    const float* hrow = hidden + (size_t)b * HID;
    const float* crow = cell + (size_t)b * HID;

    float p[SEQ];
#pragma unroll
    for (int s = 0; s < SEQ; s++) p[s] = 0.f;
    for (int k = t; k < HID; k += 128) {
        float hv = hrow[k], cv = crow[k];
#pragma unroll
        for (int s = 0; s < SEQ; s++)
            p[s] += hv * W_attn[s * 1025 + 1 + k] + cv * W_attn[s * 1025 + 513 + k];
    }
#pragma unroll
    for (int s = 0; s < SEQ; s++) red[s][t] = p[s];
    __syncthreads();
    for (int off = 64; off > 0; off >>= 1) {
        if (t < off) {
#pragma unroll
            for (int s = 0; s < SEQ; s++) red[s][t] += red[s][t + off];
        }
        __syncthreads();
    }
    if (t == 0) {
        float inp = input[b];
        float lo[SEQ];
        float mx = -1e30f;
#pragma unroll
        for (int s = 0; s < SEQ; s++) {
            lo[s] = red[s][0] + b_attn[s] + inp * W_attn[s * 1025];
            mx = fmaxf(mx, lo[s]);
        }
        float sum = 0.f;
#pragma unroll
        for (int s = 0; s < SEQ; s++) { lo[s] = expf(lo[s] - mx); sum += lo[s]; }
        float inv = 1.f / sum;
#pragma unroll
        for (int s = 0; s < SEQ; s++) {
            float w = lo[s] * inv;
            ws[s] = w;
            out_attnw[(size_t)b * SEQ + s] = w;
        }
    }
    __syncthreads();

    const float* eb = enc + (size_t)b * SEQ * HID;
    float w0 = ws[0], w1 = ws[1], w2 = ws[2], w3 = ws[3], w4 = ws[4], w5 = ws[5];
    for (int h = t; h < HID; h += 128) {
        float acc = w0 * eb[0 * HID + h] + w1 * eb[1 * HID + h] + w2 * eb[2 * HID + h]
                  + w3 * eb[3 * HID + h] + w4 * eb[4 * HID + h] + w5 * eb[5 * HID + h];
        g_attn_applied[(size_t)b * HID + h] = acc;
    }
}

// ---------------- mma.sync GEMM: C[m,n] = epi(sum_k A[m,k]*W[n,k]) -----------
// BM=128, BN=128, BK=32, 256 threads (8 warps, 4x2), warp tile 32x64.
// 3x-bf16 split passes: Ahi*Bhi + Ahi*Blo + Alo*Bhi, fp32 accum.
// GK = total K (512 or 1024; seg switch to A2/W2 at k=512, ic>=16).
// MODE 0: relu(acc + bias1[n] + rvec_m[m]*rvec_n[n])
// MODE 1: acc + bias1[n] + bias2[n]
#define SST 40   // smem K-stride in bf16 elements (80B rows -> conflict-free)

template <int MODE, int GK>
__global__ void __launch_bounds__(256)
mma_gemm(const float* __restrict__ A1, const float* __restrict__ A2,
         const float* __restrict__ W1, const float* __restrict__ W2,
         const float* __restrict__ bias1, const float* __restrict__ bias2,
         const float* __restrict__ rvec_m, const float* __restrict__ rvec_n,
         float* __restrict__ C, int ldc) {
    __shared__ __align__(16) uint16_t Ah[128 * SST];
    __shared__ __align__(16) uint16_t Al[128 * SST];
    __shared__ __align__(16) uint16_t Bh[128 * SST];
    __shared__ __align__(16) uint16_t Bl[128 * SST];

    const int tid  = threadIdx.x;
    const int lane = tid & 31;
    const int wid  = tid >> 5;
    const int wm   = wid & 3;        // 4 warps in M
    const int wn   = wid >> 2;       // 2 warps in N
    const int RM   = blockIdx.x * 128;
    const int CN   = blockIdx.y * 128;
    const int m0   = wm * 32;
    const int n0   = wn * 64;
    const int gr   = lane >> 2;      // groupID (0..7)
    const int tg   = lane & 3;       // thread-in-group

    float acc[2][8][4];
#pragma unroll
    for (int i = 0; i < 2; i++)
#pragma unroll
        for (int j = 0; j < 8; j++)
#pragma unroll
            for (int c = 0; c < 4; c++) acc[i][j][c] = 0.f;

    const int NCH = GK / 32;
#pragma unroll 1
    for (int ic = 0; ic < NCH; ic++) {
        const float* Ap;
        const float* Wp;
        int kcol;
        if (GK == 1024 && ic >= 16) { Ap = A2; Wp = W2; kcol = ic * 32 - 512; }
        else                         { Ap = A1; Wp = W1; kcol = ic * 32; }

        // Load + split A tile (128 rows x 32 k) and B tile (128 rows x 32 k)
#pragma unroll
        for (int it = 0; it < 4; it++) {
            int e = it * 256 + tid;
            int row = e >> 3, kq = e & 7;
            float4 va = *(const float4*)(Ap + (size_t)(RM + row) * 512 + kcol + kq * 4);
            uint32_t h01, h23, l01, l23;
            split4(va, h01, h23, l01, l23);
            int off = row * SST + kq * 4;
            *(uint2*)&Ah[off] = make_uint2(h01, h23);
            *(uint2*)&Al[off] = make_uint2(l01, l23);
            float4 vb = *(const float4*)(Wp + (size_t)(CN + row) * 512 + kcol + kq * 4);
            split4(vb, h01, h23, l01, l23);
            *(uint2*)&Bh[off] = make_uint2(h01, h23);
            *(uint2*)&Bl[off] = make_uint2(l01, l23);
        }
        __syncthreads();

#pragma unroll
        for (int ks = 0; ks < 2; ks++) {
            const int kb = ks * 16;
            // A fragments (hi and lo) for 2 m16 tiles
            uint32_t ah[2][4], al[2][4];
#pragma unroll
            for (int i = 0; i < 2; i++) {
                int rb = (m0 + i * 16 + gr) * SST + kb + tg * 2;
                ah[i][0] = *(const uint32_t*)&Ah[rb];
                ah[i][1] = *(const uint32_t*)&Ah[rb + 8 * SST];
                ah[i][2] = *(const uint32_t*)&Ah[rb + 8];
                ah[i][3] = *(const uint32_t*)&Ah[rb + 8 * SST + 8];
                al[i][0] = *(const uint32_t*)&Al[rb];
                al[i][1] = *(const uint32_t*)&Al[rb + 8 * SST];
                al[i][2] = *(const uint32_t*)&Al[rb + 8];
                al[i][3] = *(const uint32_t*)&Al[rb + 8 * SST + 8];
            }
#pragma unroll
            for (int j = 0; j < 8; j++) {
                int cb = (n0 + j * 8 + gr) * SST + kb + tg * 2;
                uint32_t bh0 = *(const uint32_t*)&Bh[cb];
                uint32_t bh1 = *(const uint32_t*)&Bh[cb + 8];
                uint32_t bl0 = *(const uint32_t*)&Bl[cb];
                uint32_t bl1 = *(const uint32_t*)&Bl[cb + 8];
#pragma unroll
                for (int i = 0; i < 2; i++) {
                    MMA16816(acc[i][j], ah[i], bh0, bh1);
                    MMA16816(acc[i][j], ah[i], bl0, bl1);
                    MMA16816(acc[i][j], al[i], bh0, bh1);
                }
            }
        }
        __syncthreads();
    }

    // Epilogue: c0,c1 -> (row gr, cols tg*2+0/1); c2,c3 -> (row gr+8)
#pragma unroll
    for (int i = 0; i < 2; i++) {
        int mrow0 = RM + m0 + i * 16 + gr;
        int mrow1 = mrow0 + 8;
        float rm0 = (MODE == 0) ? rvec_m[mrow0] : 0.f;
        float rm1 = (MODE == 0) ? rvec_m[mrow1] : 0.f;
#pragma unroll
        for (int j = 0; j < 8; j++) {
            int n = CN + n0 + j * 8 + tg * 2;
            float b10 = bias1[n], b11 = bias1[n + 1];
            float v00 = acc[i][j][0] + b10;
            float v01 = acc[i][j][1] + b11;
            float v10 = acc[i][j][2] + b10;
            float v11 = acc[i][j][3] + b11;
            if (MODE == 0) {
                float rn0 = rvec_n[n], rn1 = rvec_n[n + 1];
                v00 = fmaxf(v00 + rm0 * rn0, 0.f);
                v01 = fmaxf(v01 + rm0 * rn1, 0.f);
                v10 = fmaxf(v10 + rm1 * rn0, 0.f);
                v11 = fmaxf(v11 + rm1 * rn1, 0.f);
            } else {
                float b20 = bias2[n], b21 = bias2[n + 1];
                v00 += b20; v01 += b21; v10 += b20; v11 += b21;
            }
            *(float2*)(C + (size_t)mrow0 * ldc + n) = make_float2(v00, v01);
            *(float2*)(C + (size_t)mrow1 * ldc + n) = make_float2(v10, v11);
        }
    }
}

// ---------------- K4: LSTM elementwise + output GEMV ------------------------
__global__ void lstm_kernel(const float* __restrict__ cell,
                            const float* __restrict__ W_out,
                            const float* __restrict__ b_out,
                            float* __restrict__ out_y,
                            float* __restrict__ out_h,
                            float* __restrict__ out_c) {
    int b = blockIdx.x;
    int t = threadIdx.x;  // 128
    const float* g = g_gates + (size_t)b * 2048;
    const float* crow = cell + (size_t)b * HID;
    float partial = 0.f;
    for (int h = t; h < HID; h += 128) {
        float iv = g[h];
        float fv = g[512 + h];
        float gv = g[1024 + h];
        float ov = g[1536 + h];
        float si = 1.f / (1.f + expf(-iv));
        float sf = 1.f / (1.f + expf(-fv));
        float so = 1.f / (1.f + expf(-ov));
        float cn = sf * crow[h] + si * tanhf(gv);
        float hn = so * tanhf(cn);
        out_c[(size_t)b * HID + h] = cn;
        out_h[(size_t)b * HID + h] = hn;
        partial += hn * W_out[h];
    }
    __shared__ float red[128];
    red[t] = partial;
    __syncthreads();
    for (int off = 64; off > 0; off >>= 1) {
        if (t < off) red[t] += red[t + off];
        __syncthreads();
    }
    if (t == 0) out_y[b] = red[0] + b_out[0];
}

// ---------------- launch -----------------------------------------------------
extern "C" void kernel_launch(void* const* d_in, const int* in_sizes, int n_in,
                              void* d_out, int out_size) {
    const float* input   = (const float*)d_in[0];
    const float* hidden  = (const float*)d_in[1];
    const float* cell    = (const float*)d_in[2];
    const float* enc     = (const float*)d_in[3];
    const float* W_attn  = (const float*)d_in[4];
    const float* b_attn  = (const float*)d_in[5];
    const float* W_comb  = (const float*)d_in[6];
    const float* b_comb  = (const float*)d_in[7];
    const float* W_ih    = (const float*)d_in[8];
    const float* W_hh    = (const float*)d_in[9];
    const float* b_ih    = (const float*)d_in[10];
    const float* b_hh    = (const float*)d_in[11];
    const float* W_out   = (const float*)d_in[12];
    const float* b_out   = (const float*)d_in[13];

    float* out = (float*)d_out;
    float* out_y  = out;
    float* out_h  = out + BATCH;
    float* out_c  = out + BATCH + (size_t)BATCH * HID;
    float* out_aw = out + BATCH + 2 * (size_t)BATCH * HID;

    float* p_attn_applied; cudaGetSymbolAddress((void**)&p_attn_applied, g_attn_applied);
    float* p_x;            cudaGetSymbolAddress((void**)&p_x, g_x);
    float* p_gates;        cudaGetSymbolAddress((void**)&p_gates, g_gates);
    float* p_Wc2;          cudaGetSymbolAddress((void**)&p_Wc2, g_Wc2);
    float* p_wc0;          cudaGetSymbolAddress((void**)&p_wc0, g_wc0);

    // K0: repack W_comb
    pack_wcomb_kernel<<<(HID * HID + 255) / 256, 256>>>(W_comb);

    // K1: attention
    attn_kernel<<<BATCH, 128>>>(input, hidden, cell, enc, W_attn, b_attn, out_aw);

    // K2: attn_combine  (M=16384, N=512, K=512) -> g_x
    {
        dim3 grid(BATCH / 128, HID / 128);
        mma_gemm<0, 512><<<grid, 256>>>(p_attn_applied, nullptr,
                                        p_Wc2, nullptr,
                                        b_comb, nullptr,
                                        input, p_wc0,
                                        p_x, HID);
    }

    // K3: gates (M=16384, N=2048, K=1024: [x|hidden] @ [W_ih|W_hh]^T) -> g_gates
    {
        dim3 grid(BATCH / 128, (4 * HID) / 128);
        mma_gemm<1, 1024><<<grid, 256>>>(p_x, hidden,
                                         W_ih, W_hh,
                                         b_ih, b_hh,
                                         nullptr, nullptr,
                                         p_gates, 4 * HID);
    }

    // K4: LSTM elementwise + output
    lstm_kernel<<<BATCH, 128>>>(cell, W_out, b_out, out_y, out_h, out_c);
}